// round 2
// baseline (speedup 1.0000x reference)
#include <cuda_runtime.h>

#define BB   32
#define SS   1024
#define DD   64
#define CLIPD 64
#define TQ   64
#define TK   64
#define NT   256
#define PADV 68   // stride for qs/ks/vs (float4-aligned, conflict-free)
#define PADS 65   // stride for score/prob tile (scalar, conflict-free)

// smem layout (floats):
//  qs[TQ*PADV], ks[TK*PADV], vs[TK*PADV], sp[TQ*PADS], rp[TQ*129], mrow[TQ], lrow[TQ], arow[TQ]
#define SMEM_FLOATS (3*TQ*PADV + TQ*PADS + TQ*129 + 3*TQ)

__global__ void __launch_bounds__(NT, 2)
attn_relpos_kernel(const float* __restrict__ q,
                   const float* __restrict__ k,
                   const float* __restrict__ v,
                   const int* __restrict__ mask,
                   const float* __restrict__ pt,
                   float* __restrict__ out) {
    extern __shared__ float sm[];
    float* qs   = sm;
    float* ks   = qs + TQ * PADV;
    float* vs   = ks + TK * PADV;
    float* sp   = vs + TK * PADV;
    float* rp   = sp + TQ * PADS;
    float* mrow = rp + TQ * 129;
    float* lrow = mrow + TQ;
    float* arow = lrow + TQ;

    const int tid = threadIdx.x;
    const int qt  = blockIdx.x;
    const int b   = blockIdx.y;
    const int qg0 = qt * TQ;
    const float scale = 0.125f;  // 1/sqrt(64)

    // ---- load Q tile (float4, coalesced) ----
    {
        const float4* qg = (const float4*)(q + ((size_t)b * SS + qg0) * DD);
        for (int i = tid; i < TQ * 16; i += NT) {
            int r = i >> 4, c = i & 15;
            float4 val = qg[r * 16 + c];
            float* dst = qs + r * PADV + c * 4;
            dst[0] = val.x; dst[1] = val.y; dst[2] = val.z; dst[3] = val.w;
        }
    }
    __syncthreads();

    // ---- precompute rel-pos logits: rp[r][j] = dot(qs[r,:], pos_table[j,:]) ----
    for (int i = tid; i < TQ * 129; i += NT) {
        int r = i / 129, j = i - r * 129;
        const float4* ptj = (const float4*)(pt + j * DD);
        const float*  qr  = qs + r * PADV;
        float acc = 0.f;
        #pragma unroll
        for (int c = 0; c < 16; c++) {
            float4 pv = ptj[c];
            acc += qr[c*4+0] * pv.x + qr[c*4+1] * pv.y
                 + qr[c*4+2] * pv.z + qr[c*4+3] * pv.w;
        }
        rp[r * 129 + j] = acc;
    }
    if (tid < TQ) { mrow[tid] = -1e30f; lrow[tid] = 0.f; }

    // ---- per-thread state ----
    const int sr  = tid >> 2;        // score/softmax row (0..63), 4 threads per row
    const int sj  = tid & 3;         // key sub-lane: keys kx = kk*4 + sj
    const int ar  = tid & 63;        // accumulation row (0..63)
    const int ad0 = (tid >> 6) * 16; // 16 output dims per thread

    float acc[16];
    #pragma unroll
    for (int i = 0; i < 16; i++) acc[i] = 0.f;

    const float* kbase = k + ((size_t)b * SS) * DD;
    const float* vbase = v + ((size_t)b * SS) * DD;
    const int* mbase = mask + ((size_t)b * SS + (qg0 + sr)) * (size_t)SS;

    for (int kt = 0; kt < SS / TK; kt++) {
        const int kg0 = kt * TK;
        __syncthreads();  // previous acc step done reading ks/vs/sp

        // ---- load K,V tiles ----
        {
            const float4* kg = (const float4*)(kbase + (size_t)kg0 * DD);
            const float4* vg = (const float4*)(vbase + (size_t)kg0 * DD);
            for (int i = tid; i < TK * 16; i += NT) {
                int r = i >> 4, c = i & 15;
                float4 kv4 = kg[r * 16 + c];
                float4 vv4 = vg[r * 16 + c];
                float* kd = ks + r * PADV + c * 4;
                kd[0] = kv4.x; kd[1] = kv4.y; kd[2] = kv4.z; kd[3] = kv4.w;
                float* vd = vs + r * PADV + c * 4;
                vd[0] = vv4.x; vd[1] = vv4.y; vd[2] = vv4.z; vd[3] = vv4.w;
            }
        }
        __syncthreads();

        // ---- scores: thread computes 16 logits for row sr, keys kk*4+sj ----
        float sc[16];
        #pragma unroll
        for (int kk = 0; kk < 16; kk++) sc[kk] = 0.f;
        {
            const float* qr = qs + sr * PADV;
            #pragma unroll
            for (int c = 0; c < 16; c++) {
                float4 qv = *(const float4*)(qr + c * 4);
                #pragma unroll
                for (int kk = 0; kk < 16; kk++) {
                    float4 kvv = *(const float4*)(ks + (kk * 4 + sj) * PADV + c * 4);
                    sc[kk] += qv.x * kvv.x + qv.y * kvv.y + qv.z * kvv.z + qv.w * kvv.w;
                }
            }
        }

        // ---- rel-pos add, scale, mask (mask stored as int32; nonzero => -inf) ----
        const int* mr = mbase + kg0;
        #pragma unroll
        for (int kk = 0; kk < 16; kk++) {
            int kx = kk * 4 + sj;
            int rel = (kg0 + kx) - (qg0 + sr);
            rel = min(max(rel, -CLIPD), CLIPD);
            float sv = (sc[kk] + rp[sr * 129 + rel + CLIPD]) * scale;
            if (mr[kx]) sv = -1e30f;
            sc[kk] = sv;
        }

        // ---- online softmax (group-of-4 shuffle reduce, same warp) ----
        float tmax = -1e30f;
        #pragma unroll
        for (int kk = 0; kk < 16; kk++) tmax = fmaxf(tmax, sc[kk]);
        tmax = fmaxf(tmax, __shfl_xor_sync(0xffffffffu, tmax, 1));
        tmax = fmaxf(tmax, __shfl_xor_sync(0xffffffffu, tmax, 2));

        float mold = mrow[sr];
        float mnew = fmaxf(mold, tmax);
        float alpha = __expf(mold - mnew);

        float psum = 0.f;
        #pragma unroll
        for (int kk = 0; kk < 16; kk++) {
            float p = __expf(sc[kk] - mnew);
            psum += p;
            sp[sr * PADS + kk * 4 + sj] = p;
        }
        psum += __shfl_xor_sync(0xffffffffu, psum, 1);
        psum += __shfl_xor_sync(0xffffffffu, psum, 2);
        if (sj == 0) {
            mrow[sr] = mnew;
            lrow[sr] = lrow[sr] * alpha + psum;
            arow[sr] = alpha;
        }
        __syncthreads();

        // ---- acc update: thread owns row ar, dims [ad0, ad0+16) ----
        {
            float al = arow[ar];
            #pragma unroll
            for (int dd = 0; dd < 16; dd++) acc[dd] *= al;
            const float* prow = sp + ar * PADS;
            #pragma unroll 4
            for (int kx = 0; kx < TK; kx++) {
                float p = prow[kx];
                const float4* vr = (const float4*)(vs + kx * PADV + ad0);
                float4 v0 = vr[0], v1 = vr[1], v2 = vr[2], v3 = vr[3];
                acc[0]  += p * v0.x; acc[1]  += p * v0.y; acc[2]  += p * v0.z; acc[3]  += p * v0.w;
                acc[4]  += p * v1.x; acc[5]  += p * v1.y; acc[6]  += p * v1.z; acc[7]  += p * v1.w;
                acc[8]  += p * v2.x; acc[9]  += p * v2.y; acc[10] += p * v2.z; acc[11] += p * v2.w;
                acc[12] += p * v3.x; acc[13] += p * v3.y; acc[14] += p * v3.z; acc[15] += p * v3.w;
            }
        }
    }

    // ---- finalize: out[b, qg0+ar, ad0:ad0+16] = acc / l ----
    float invl = 1.0f / lrow[ar];
    float* og = out + (((size_t)b * SS + qg0 + ar) * DD + ad0);
    #pragma unroll
    for (int c = 0; c < 4; c++) {
        float4 o;
        o.x = acc[c*4+0] * invl;
        o.y = acc[c*4+1] * invl;
        o.z = acc[c*4+2] * invl;
        o.w = acc[c*4+3] * invl;
        ((float4*)og)[c] = o;
    }
}

extern "C" void kernel_launch(void* const* d_in, const int* in_sizes, int n_in,
                              void* d_out, int out_size) {
    const float* q    = (const float*)d_in[0];
    const float* k    = (const float*)d_in[1];
    const float* v    = (const float*)d_in[2];
    const int*   mask = (const int*)d_in[3];
    const float* pt   = (const float*)d_in[4];
    float*       out  = (float*)d_out;

    size_t smem = SMEM_FLOATS * sizeof(float);
    cudaFuncSetAttribute(attn_relpos_kernel,
                         cudaFuncAttributeMaxDynamicSharedMemorySize, (int)smem);

    dim3 grid(SS / TQ, BB);
    attn_relpos_kernel<<<grid, NT, smem>>>(q, k, v, mask, pt, out);
}

// round 3
// speedup vs baseline: 1.7158x; 1.7158x over previous
#include <cuda_runtime.h>

#define BB   32
#define SS   1024
#define DD   64
#define CLIPD 64
#define TQ   64
#define TK   64
#define NT   256

// smem float offsets
#define QS_OFF   0                 // 64 x 64   (row-major, stride 64)
#define KS_OFF   (QS_OFF + 64*64)  // 64 x 68   (row-major, stride 68: 2-way-conflict lane stride)
#define VS_OFF   (KS_OFF + 64*68)  // 64 x 64   (row-major, stride 64)
#define SPD_OFF  (VS_OFF + 64*64)  // 64 x 128  (probs duplicated: [r][2*kx] = [r][2*kx+1] = p)
#define RP_OFF   (SPD_OFF + 64*128) // 64 x 129
#define SMEM_FLOATS (RP_OFF + 64*129)   // 28992 floats = 113.25 KB

typedef unsigned long long ull;

__device__ __forceinline__ void fma2(ull& d, ull a, ull b) {
    asm("fma.rn.f32x2 %0, %1, %2, %0;" : "+l"(d) : "l"(a), "l"(b));
}
__device__ __forceinline__ void mul2(ull& d, ull a, ull b) {
    asm("mul.rn.f32x2 %0, %1, %2;" : "=l"(d) : "l"(a), "l"(b));
}
__device__ __forceinline__ ull packf2(float lo, float hi) {
    ull r; asm("mov.b64 %0, {%1, %2};" : "=l"(r) : "f"(lo), "f"(hi)); return r;
}
__device__ __forceinline__ float2 unpackf2(ull x) {
    float2 r; asm("mov.b64 {%0, %1}, %2;" : "=f"(r.x), "=f"(r.y) : "l"(x)); return r;
}

__global__ void __launch_bounds__(NT, 2)
attn_relpos_kernel(const float* __restrict__ q,
                   const float* __restrict__ k,
                   const float* __restrict__ v,
                   const int* __restrict__ mask,
                   const float* __restrict__ pt,
                   float* __restrict__ out) {
    extern __shared__ float sm[];
    float* qs  = sm + QS_OFF;
    float* ks  = sm + KS_OFF;
    float* vs  = sm + VS_OFF;
    float* spd = sm + SPD_OFF;
    float* rp  = sm + RP_OFF;

    const int tid = threadIdx.x;
    const int qt  = blockIdx.x;
    const int b   = blockIdx.y;
    const int qg0 = qt * TQ;
    const float scale = 0.125f;

    const int tkx = tid & 15;   // key lane / dim group
    const int trg = tid >> 4;   // row group 0..15
    const int r0  = trg * 4;    // rows r0..r0+3
    const int d0  = tkx * 4;    // output dims d0..d0+3

    // ---- load Q tile into smem (row-major, stride 64) ----
    {
        const float4* qg = (const float4*)(q + ((size_t)b * SS + qg0) * DD);
        #pragma unroll
        for (int l = 0; l < 4; l++) {
            int f = tid + l * NT;           // float4 index 0..1023
            int r = f >> 4, c4 = f & 15;
            float4 val = qg[f];
            *(float4*)(qs + r * 64 + c4 * 4) = val;
        }
    }
    __syncthreads();

    // ---- rel-pos logits rp[r][j] = q[r,:] . pt[j,:] ----
    {
        const int rr = tid >> 2;
        const int jg = tid & 3;
        const float4* ptg = (const float4*)pt;
        for (int j = jg; j < 2 * CLIPD + 1; j += 4) {
            float acc = 0.f;
            #pragma unroll
            for (int c4 = 0; c4 < 16; c4++) {
                float4 a = *(const float4*)(qs + rr * 64 + c4 * 4);
                float4 p4 = ptg[j * 16 + c4];
                acc += a.x * p4.x + a.y * p4.y + a.z * p4.z + a.w * p4.w;
            }
            rp[rr * 129 + j] = acc;
        }
    }
    __syncthreads();

    // per-row register state
    float rpn[4], rpp[4], mR[4], lR[4];
    #pragma unroll
    for (int i = 0; i < 4; i++) {
        rpn[i] = rp[(r0 + i) * 129 + 0];
        rpp[i] = rp[(r0 + i) * 129 + 128];
        mR[i] = -1e30f; lR[i] = 0.f;
    }

    ull acc2[4][2];
    #pragma unroll
    for (int i = 0; i < 4; i++) { acc2[i][0] = 0ull; acc2[i][1] = 0ull; }

    const float* kbase = k + ((size_t)b * SS) * DD;
    const float* vbase = v + ((size_t)b * SS) * DD;
    const int*   mbase = mask + ((size_t)b * SS + qg0 + r0) * (size_t)SS + tkx;

    for (int kt = 0; kt < SS / TK; kt++) {
        const int kg0 = kt * TK;
        const int D   = kg0 - qg0;
        __syncthreads();  // previous tile fully consumed

        // ---- copy K (stride 68) and V (stride 64) tiles ----
        {
            const float4* kg = (const float4*)(kbase + (size_t)kg0 * DD);
            const float4* vg = (const float4*)(vbase + (size_t)kg0 * DD);
            #pragma unroll
            for (int l = 0; l < 4; l++) {
                int f = tid + l * NT;
                int r = f >> 4, c4 = f & 15;
                float4 kv4 = kg[f];
                float4 vv4 = vg[f];
                *(float4*)(ks + r * 68 + c4 * 4) = kv4;
                *(float4*)(vs + r * 64 + c4 * 4) = vv4;
            }
        }

        // ---- prefetch mask (int32; nonzero => -inf). keys kx = tkx + 16j ----
        int msk[4][4];
        #pragma unroll
        for (int i = 0; i < 4; i++) {
            const int* mr = mbase + (size_t)i * SS + kg0;
            #pragma unroll
            for (int j = 0; j < 4; j++) msk[i][j] = mr[16 * j];
        }
        __syncthreads();  // tiles ready

        // ---- scores: rows r0..r0+3  x  keys {tkx+16j}, packed over reduction dim ----
        ull sc2[4][4];
        #pragma unroll
        for (int i = 0; i < 4; i++)
            #pragma unroll
            for (int j = 0; j < 4; j++) sc2[i][j] = 0ull;

        #pragma unroll 4
        for (int c4 = 0; c4 < 16; c4++) {
            ulonglong2 qv[4], kv[4];
            #pragma unroll
            for (int i = 0; i < 4; i++)
                qv[i] = *(const ulonglong2*)(qs + (r0 + i) * 64 + c4 * 4);
            #pragma unroll
            for (int j = 0; j < 4; j++)
                kv[j] = *(const ulonglong2*)(ks + (tkx + 16 * j) * 68 + c4 * 4);
            #pragma unroll
            for (int i = 0; i < 4; i++)
                #pragma unroll
                for (int j = 0; j < 4; j++) {
                    fma2(sc2[i][j], qv[i].x, kv[j].x);
                    fma2(sc2[i][j], qv[i].y, kv[j].y);
                }
        }

        // ---- reduce pairs, add rel-pos, scale, mask ----
        float s[4][4];
        const bool far = (D <= -127) || (D >= 127);
        #pragma unroll
        for (int i = 0; i < 4; i++) {
            #pragma unroll
            for (int j = 0; j < 4; j++) {
                float2 t = unpackf2(sc2[i][j]);
                float dot = t.x + t.y;
                float rpv;
                if (far) {
                    rpv = (D > 0) ? rpp[i] : rpn[i];
                } else {
                    int rel = D + (tkx + 16 * j) - (r0 + i);
                    rel = min(max(rel, -CLIPD), CLIPD);
                    rpv = rp[(r0 + i) * 129 + rel + CLIPD];
                }
                float sv = (dot + rpv) * scale;
                s[i][j] = msk[i][j] ? -1e30f : sv;
            }
        }

        // ---- online softmax: reduce over 16-lane group (xor 1,2,4,8) ----
        #pragma unroll
        for (int i = 0; i < 4; i++) {
            float tm = fmaxf(fmaxf(s[i][0], s[i][1]), fmaxf(s[i][2], s[i][3]));
            #pragma unroll
            for (int off = 1; off <= 8; off <<= 1)
                tm = fmaxf(tm, __shfl_xor_sync(0xffffffffu, tm, off));
            float mnew = fmaxf(mR[i], tm);
            float p0 = __expf(s[i][0] - mnew);
            float p1 = __expf(s[i][1] - mnew);
            float p2 = __expf(s[i][2] - mnew);
            float p3 = __expf(s[i][3] - mnew);
            float ps = (p0 + p1) + (p2 + p3);
            #pragma unroll
            for (int off = 1; off <= 8; off <<= 1)
                ps += __shfl_xor_sync(0xffffffffu, ps, off);
            float alpha = __expf(mR[i] - mnew);
            lR[i] = lR[i] * alpha + ps;
            mR[i] = mnew;
            // rescale accumulator
            ull aa = packf2(alpha, alpha);
            mul2(acc2[i][0], acc2[i][0], aa);
            mul2(acc2[i][1], acc2[i][1], aa);
            // store duplicated probs: spd[r][2*kx], kx = tkx+16j
            float* sr = spd + (r0 + i) * 128 + 2 * tkx;
            *(ull*)(sr + 0)  = packf2(p0, p0);
            *(ull*)(sr + 32) = packf2(p1, p1);
            *(ull*)(sr + 64) = packf2(p2, p2);
            *(ull*)(sr + 96) = packf2(p3, p3);
        }
        __syncwarp();

        // ---- PV accumulate: acc[i][d0..d0+3] += p * v, packed over dims ----
        #pragma unroll 4
        for (int kx2 = 0; kx2 < 32; kx2++) {
            ulonglong2 va = *(const ulonglong2*)(vs + (2 * kx2)     * 64 + d0);
            ulonglong2 vb = *(const ulonglong2*)(vs + (2 * kx2 + 1) * 64 + d0);
            #pragma unroll
            for (int i = 0; i < 4; i++) {
                ulonglong2 pp = *(const ulonglong2*)(spd + (r0 + i) * 128 + 4 * kx2);
                fma2(acc2[i][0], pp.x, va.x);
                fma2(acc2[i][1], pp.x, va.y);
                fma2(acc2[i][0], pp.y, vb.x);
                fma2(acc2[i][1], pp.y, vb.y);
            }
        }
        __syncwarp();
    }

    // ---- finalize ----
    #pragma unroll
    for (int i = 0; i < 4; i++) {
        float invl = 1.0f / lR[i];
        float2 a0 = unpackf2(acc2[i][0]);
        float2 a1 = unpackf2(acc2[i][1]);
        float4 o;
        o.x = a0.x * invl; o.y = a0.y * invl;
        o.z = a1.x * invl; o.w = a1.y * invl;
        *(float4*)(out + ((size_t)b * SS + qg0 + r0 + i) * DD + d0) = o;
    }
}

extern "C" void kernel_launch(void* const* d_in, const int* in_sizes, int n_in,
                              void* d_out, int out_size) {
    const float* q    = (const float*)d_in[0];
    const float* k    = (const float*)d_in[1];
    const float* v    = (const float*)d_in[2];
    const int*   mask = (const int*)d_in[3];
    const float* pt   = (const float*)d_in[4];
    float*       out  = (float*)d_out;

    size_t smem = SMEM_FLOATS * sizeof(float);
    cudaFuncSetAttribute(attn_relpos_kernel,
                         cudaFuncAttributeMaxDynamicSharedMemorySize, (int)smem);

    dim3 grid(SS / TQ, BB);
    attn_relpos_kernel<<<grid, NT, smem>>>(q, k, v, mask, pt, out);
}

// round 4
// speedup vs baseline: 3.9478x; 2.3009x over previous
#include <cuda_runtime.h>
#include <cstdint>

#define BB 32
#define SS 1024
#define DD 64
#define TQ 64
#define TK 64
#define NT 128

#define KS_STRIDE 68
#define VS_STRIDE 72
#define RP_STRIDE 129
#define PT_STRIDE 136

// smem float offsets
#define KS_OFF 0
#define VS_OFF (KS_OFF + 64*KS_STRIDE)          // 4352
#define RP_OFF (VS_OFF + 64*VS_STRIDE)          // 8960
#define QS_OFF (RP_OFF + 64*RP_STRIDE)          // 17216
#define SMEM_FLOATS (QS_OFF + 64*64)            // 21312 floats = 85248 B
#define PT_OFF KS_OFF                           // pt_t aliases ks+vs region (8704 <= 8960 floats)

__device__ unsigned g_mbits[(size_t)BB * SS * SS / 32];   // 4 MB packed mask bits

// ---- mask bit-pack: one warp packs 32 consecutive int32 flags into one word ----
__global__ void pack_mask_kernel(const int* __restrict__ mask) {
    int g = blockIdx.x * blockDim.x + threadIdx.x;
    int v = mask[g] != 0;
    unsigned bal = __ballot_sync(0xffffffffu, v);
    if ((threadIdx.x & 31) == 0) g_mbits[g >> 5] = bal;
}

__device__ __forceinline__ unsigned f2tf(float f) {
    unsigned u; asm("cvt.rna.tf32.f32 %0, %1;" : "=r"(u) : "f"(f)); return u;
}
__device__ __forceinline__ void mma_tf32(float c[4], const unsigned a[4],
                                         unsigned b0, unsigned b1) {
    asm volatile(
        "mma.sync.aligned.m16n8k8.row.col.f32.tf32.tf32.f32 "
        "{%0,%1,%2,%3}, {%4,%5,%6,%7}, {%8,%9}, {%0,%1,%2,%3};"
        : "+f"(c[0]), "+f"(c[1]), "+f"(c[2]), "+f"(c[3])
        : "r"(a[0]), "r"(a[1]), "r"(a[2]), "r"(a[3]), "r"(b0), "r"(b1));
}

// rp-table GEMM chunk: rp[r][j] = q[r,:] . pt[j,:], standard C layout
template<int NB0, int NBN>
__device__ __forceinline__ void rp_mma_chunk(const unsigned aq[8][4], const float* ptt,
                                             float* rp, int r0, int r1, int u, int g) {
    float c[NBN][4];
    #pragma unroll
    for (int n = 0; n < NBN; n++) { c[n][0]=0.f; c[n][1]=0.f; c[n][2]=0.f; c[n][3]=0.f; }
    #pragma unroll
    for (int s = 0; s < 8; s++) {
        #pragma unroll
        for (int n = 0; n < NBN; n++) {
            int jr = (NB0 + n) * 8 + g;
            unsigned b0 = __float_as_uint(ptt[(8*s + u)     * PT_STRIDE + jr]);
            unsigned b1 = __float_as_uint(ptt[(8*s + u + 4) * PT_STRIDE + jr]);
            mma_tf32(c[n], aq[s], b0, b1);
        }
    }
    #pragma unroll
    for (int n = 0; n < NBN; n++) {
        int col = (NB0 + n) * 8 + 2 * u;
        if (col <= 128)     { rp[r0*RP_STRIDE + col]     = c[n][0]; rp[r1*RP_STRIDE + col]     = c[n][2]; }
        if (col + 1 <= 128) { rp[r0*RP_STRIDE + col + 1] = c[n][1]; rp[r1*RP_STRIDE + col + 1] = c[n][3]; }
    }
}

__global__ void __launch_bounds__(NT, 2)
attn_tc_kernel(const float* __restrict__ q,
               const float* __restrict__ k,
               const float* __restrict__ v,
               const float* __restrict__ pt,
               float* __restrict__ out) {
    extern __shared__ float sm[];
    float* ks  = sm + KS_OFF;
    float* vs  = sm + VS_OFF;
    float* rp  = sm + RP_OFF;
    float* qs  = sm + QS_OFF;
    float* ptt = sm + PT_OFF;

    const int tid  = threadIdx.x;
    const int lane = tid & 31;
    const int w    = tid >> 5;       // warp 0..3
    const int u    = lane & 3;       // quad lane
    const int g    = lane >> 2;      // group 0..7
    const int qt   = blockIdx.x, b = blockIdx.y;
    const int qg0  = qt * TQ;
    const int r0   = 16 * w + g;     // tile-local rows owned by this thread
    const int r1   = r0 + 8;
    const int keysel = (g >> 1) + 4 * (g & 1);   // sigma(g): key permutation within 8-block

    // ---- phase 0: stage Q tile and transposed tf32 pos_table ----
    {
        const float4* qg = (const float4*)(q + ((size_t)b * SS + qg0) * DD);
        for (int i = tid; i < TQ * 16; i += NT) {
            float4 val = qg[i];
            *(float4*)(qs + (i >> 4) * 64 + (i & 15) * 4) = val;
        }
        const float4* ptg = (const float4*)pt;
        for (int i = tid; i < 129 * 16; i += NT) {
            int j = i >> 4, c0 = (i & 15) * 4;
            float4 p4 = ptg[i];
            ptt[(c0 + 0) * PT_STRIDE + j] = __uint_as_float(f2tf(p4.x));
            ptt[(c0 + 1) * PT_STRIDE + j] = __uint_as_float(f2tf(p4.y));
            ptt[(c0 + 2) * PT_STRIDE + j] = __uint_as_float(f2tf(p4.z));
            ptt[(c0 + 3) * PT_STRIDE + j] = __uint_as_float(f2tf(p4.w));
        }
        for (int i = tid; i < 64 * 7; i += NT)      // zero-pad j = 129..135
            ptt[(i / 7) * PT_STRIDE + 129 + (i % 7)] = 0.f;
    }
    __syncthreads();

    // ---- phase 1: Q fragments (held all kernel) + rp table via MMA ----
    unsigned aq[8][4];
    #pragma unroll
    for (int s = 0; s < 8; s++) {
        aq[s][0] = f2tf(qs[r0 * 64 + 8*s + u]);
        aq[s][1] = f2tf(qs[r1 * 64 + 8*s + u]);
        aq[s][2] = f2tf(qs[r0 * 64 + 8*s + u + 4]);
        aq[s][3] = f2tf(qs[r1 * 64 + 8*s + u + 4]);
    }
    rp_mma_chunk<0, 9>(aq, ptt, rp, r0, r1, u, g);
    rp_mma_chunk<9, 8>(aq, ptt, rp, r0, r1, u, g);
    __syncthreads();

    const float rpn0 = rp[r0 * RP_STRIDE + 0],   rpn1 = rp[r1 * RP_STRIDE + 0];
    const float rpp0 = rp[r0 * RP_STRIDE + 128], rpp1 = rp[r1 * RP_STRIDE + 128];

    float m0 = -1e30f, m1 = -1e30f, l0 = 0.f, l1 = 0.f;
    float co[8][4];
    #pragma unroll
    for (int j = 0; j < 8; j++) { co[j][0]=0.f; co[j][1]=0.f; co[j][2]=0.f; co[j][3]=0.f; }

    const unsigned* mrow0 = g_mbits + (size_t)(b * SS + qg0 + r0) * (SS / 32);
    const unsigned* mrow1 = g_mbits + (size_t)(b * SS + qg0 + r1) * (SS / 32);
    const float4* kg = (const float4*)(k + (size_t)b * SS * DD);
    const float4* vg = (const float4*)(v + (size_t)b * SS * DD);

    for (int kt = 0; kt < SS / TK; kt++) {
        const int kg0 = kt * TK;
        const int D   = kg0 - qg0;
        __syncthreads();   // previous tile fully consumed

        // ---- stage K (stride 68) / V (stride 72), converted to tf32 bits ----
        for (int i = tid; i < TK * 16; i += NT) {
            int key = i >> 4, c0 = (i & 15) * 4;
            float4 kv = kg[kg0 * 16 + i];
            float4 vv = vg[kg0 * 16 + i];
            float* kd = ks + key * KS_STRIDE + c0;
            kd[0] = __uint_as_float(f2tf(kv.x)); kd[1] = __uint_as_float(f2tf(kv.y));
            kd[2] = __uint_as_float(f2tf(kv.z)); kd[3] = __uint_as_float(f2tf(kv.w));
            float* vd = vs + key * VS_STRIDE + c0;
            vd[0] = __uint_as_float(f2tf(vv.x)); vd[1] = __uint_as_float(f2tf(vv.y));
            vd[2] = __uint_as_float(f2tf(vv.z)); vd[3] = __uint_as_float(f2tf(vv.w));
        }
        __syncthreads();

        // ---- QK^T: c[j] covers keys {8j+u, 8j+u+4} x rows {r0, r1} (sigma layout) ----
        float c[8][4];
        #pragma unroll
        for (int j = 0; j < 8; j++) { c[j][0]=0.f; c[j][1]=0.f; c[j][2]=0.f; c[j][3]=0.f; }
        #pragma unroll
        for (int s = 0; s < 8; s++) {
            #pragma unroll
            for (int j = 0; j < 8; j++) {
                unsigned b0 = __float_as_uint(ks[(8*j + keysel) * KS_STRIDE + 8*s + u]);
                unsigned b1 = __float_as_uint(ks[(8*j + keysel) * KS_STRIDE + 8*s + u + 4]);
                mma_tf32(c[j], aq[s], b0, b1);
            }
        }

        // ---- epilogue: rel-pos + scale + mask ----
        const unsigned mw0a = mrow0[2*kt], mw0b = mrow0[2*kt + 1];
        const unsigned mw1a = mrow1[2*kt], mw1b = mrow1[2*kt + 1];
        const bool nearT = (D >= -64) && (D <= 64);
        #pragma unroll
        for (int j = 0; j < 8; j++) {
            const int col0 = 8*j + u, col1 = col0 + 4;
            float rv00, rv01, rv10, rv11;
            if (nearT) {
                int i00 = min(max(D + col0 - r0, -64), 64) + 64;
                int i01 = min(max(D + col1 - r0, -64), 64) + 64;
                int i10 = min(max(D + col0 - r1, -64), 64) + 64;
                int i11 = min(max(D + col1 - r1, -64), 64) + 64;
                rv00 = rp[r0 * RP_STRIDE + i00]; rv01 = rp[r0 * RP_STRIDE + i01];
                rv10 = rp[r1 * RP_STRIDE + i10]; rv11 = rp[r1 * RP_STRIDE + i11];
            } else if (D > 0) {
                rv00 = rpp0; rv01 = rpp0; rv10 = rpp1; rv11 = rpp1;
            } else {
                rv00 = rpn0; rv01 = rpn0; rv10 = rpn1; rv11 = rpn1;
            }
            float s00 = (c[j][0] + rv00) * 0.125f;
            float s01 = (c[j][1] + rv01) * 0.125f;
            float s10 = (c[j][2] + rv10) * 0.125f;
            float s11 = (c[j][3] + rv11) * 0.125f;
            const unsigned w0 = (j < 4) ? mw0a : mw0b;
            const unsigned w1 = (j < 4) ? mw1a : mw1b;
            if ((w0 >> (col0 & 31)) & 1) s00 = -3.0e38f;
            if ((w0 >> (col1 & 31)) & 1) s01 = -3.0e38f;
            if ((w1 >> (col0 & 31)) & 1) s10 = -3.0e38f;
            if ((w1 >> (col1 & 31)) & 1) s11 = -3.0e38f;
            c[j][0] = s00; c[j][1] = s01; c[j][2] = s10; c[j][3] = s11;
        }

        // ---- online softmax (row reductions stay inside the quad) ----
        float t0 = -3.0e38f, t1 = -3.0e38f;
        #pragma unroll
        for (int j = 0; j < 8; j++) {
            t0 = fmaxf(t0, fmaxf(c[j][0], c[j][1]));
            t1 = fmaxf(t1, fmaxf(c[j][2], c[j][3]));
        }
        t0 = fmaxf(t0, __shfl_xor_sync(0xffffffffu, t0, 1));
        t0 = fmaxf(t0, __shfl_xor_sync(0xffffffffu, t0, 2));
        t1 = fmaxf(t1, __shfl_xor_sync(0xffffffffu, t1, 1));
        t1 = fmaxf(t1, __shfl_xor_sync(0xffffffffu, t1, 2));

        const float mn0 = fmaxf(m0, t0), mn1 = fmaxf(m1, t1);
        const float al0 = __expf(m0 - mn0), al1 = __expf(m1 - mn1);
        float ps0 = 0.f, ps1 = 0.f;
        #pragma unroll
        for (int j = 0; j < 8; j++) {
            float p00 = __expf(c[j][0] - mn0);
            float p01 = __expf(c[j][1] - mn0);
            float p10 = __expf(c[j][2] - mn1);
            float p11 = __expf(c[j][3] - mn1);
            ps0 += p00 + p01; ps1 += p10 + p11;
            c[j][0] = p00; c[j][1] = p01; c[j][2] = p10; c[j][3] = p11;
        }
        ps0 += __shfl_xor_sync(0xffffffffu, ps0, 1);
        ps0 += __shfl_xor_sync(0xffffffffu, ps0, 2);
        ps1 += __shfl_xor_sync(0xffffffffu, ps1, 1);
        ps1 += __shfl_xor_sync(0xffffffffu, ps1, 2);
        l0 = l0 * al0 + ps0; m0 = mn0;
        l1 = l1 * al1 + ps1; m1 = mn1;
        #pragma unroll
        for (int j = 0; j < 8; j++) {
            co[j][0] *= al0; co[j][1] *= al0;
            co[j][2] *= al1; co[j][3] *= al1;
        }

        // ---- PV: A frags = pure register renaming of P (sigma layout) ----
        #pragma unroll
        for (int s = 0; s < 8; s++) {
            unsigned a[4] = { f2tf(c[s][0]), f2tf(c[s][2]), f2tf(c[s][1]), f2tf(c[s][3]) };
            #pragma unroll
            for (int j = 0; j < 8; j++) {
                unsigned b0 = __float_as_uint(vs[(8*s + u)     * VS_STRIDE + 8*j + g]);
                unsigned b1 = __float_as_uint(vs[(8*s + u + 4) * VS_STRIDE + 8*j + g]);
                mma_tf32(co[j], a, b0, b1);
            }
        }
    }

    // ---- finalize ----
    const float il0 = 1.0f / l0, il1 = 1.0f / l1;
    float* o0 = out + (size_t)(b * SS + qg0 + r0) * DD;
    float* o1 = out + (size_t)(b * SS + qg0 + r1) * DD;
    #pragma unroll
    for (int j = 0; j < 8; j++) {
        int col = 8*j + 2*u;
        float2 v0; v0.x = co[j][0] * il0; v0.y = co[j][1] * il0;
        float2 v1; v1.x = co[j][2] * il1; v1.y = co[j][3] * il1;
        *(float2*)(o0 + col) = v0;
        *(float2*)(o1 + col) = v1;
    }
}

extern "C" void kernel_launch(void* const* d_in, const int* in_sizes, int n_in,
                              void* d_out, int out_size) {
    const float* q    = (const float*)d_in[0];
    const float* k    = (const float*)d_in[1];
    const float* v    = (const float*)d_in[2];
    const int*   mask = (const int*)d_in[3];
    const float* pt   = (const float*)d_in[4];
    float*       out  = (float*)d_out;

    pack_mask_kernel<<<(BB * SS * SS) / 256, 256>>>(mask);

    size_t smem = SMEM_FLOATS * sizeof(float);
    cudaFuncSetAttribute(attn_tc_kernel,
                         cudaFuncAttributeMaxDynamicSharedMemorySize, (int)smem);
    dim3 grid(SS / TQ, BB);
    attn_tc_kernel<<<grid, NT, smem>>>(q, k, v, pt, out);
}

// round 5
// speedup vs baseline: 5.2420x; 1.3278x over previous
#include <cuda_runtime.h>
#include <cstdint>

#define BB 32
#define SS 1024
#define DD 64
#define TQ 64
#define TK 64
#define NT 128

#define KS_STRIDE 68
#define VS_STRIDE 72
#define RP_STRIDE 129
#define PT_STRIDE 136

// smem float offsets (no Q staging buffer anymore)
#define KS_OFF 0
#define VS_OFF (KS_OFF + 64*KS_STRIDE)          // 4352
#define RP_OFF (VS_OFF + 64*VS_STRIDE)          // 8960
#define SMEM_FLOATS (RP_OFF + 64*RP_STRIDE)     // 17216 floats = 68864 B -> 3 CTAs/SM
#define PT_OFF KS_OFF                           // pt_t aliases ks+vs region (8704 <= 8960 floats)

__device__ unsigned g_mbits[(size_t)BB * SS * SS / 32];   // 4 MB packed mask bits

// ---- mask bit-pack: one thread builds one 32-bit word from 8 int4 loads ----
__global__ void pack_mask_kernel(const int* __restrict__ mask) {
    size_t wix = (size_t)blockIdx.x * blockDim.x + threadIdx.x;   // word index
    const int4* m4 = (const int4*)mask + wix * 8;
    unsigned bits = 0;
    #pragma unroll
    for (int j = 0; j < 8; j++) {
        int4 v4 = m4[j];
        bits |= (unsigned)(v4.x != 0) << (4*j + 0);
        bits |= (unsigned)(v4.y != 0) << (4*j + 1);
        bits |= (unsigned)(v4.z != 0) << (4*j + 2);
        bits |= (unsigned)(v4.w != 0) << (4*j + 3);
    }
    g_mbits[wix] = bits;
}

__device__ __forceinline__ unsigned f2tf(float f) {
    unsigned u; asm("cvt.rna.tf32.f32 %0, %1;" : "=r"(u) : "f"(f)); return u;
}
__device__ __forceinline__ void mma_tf32(float c[4], const unsigned a[4],
                                         unsigned b0, unsigned b1) {
    asm volatile(
        "mma.sync.aligned.m16n8k8.row.col.f32.tf32.tf32.f32 "
        "{%0,%1,%2,%3}, {%4,%5,%6,%7}, {%8,%9}, {%0,%1,%2,%3};"
        : "+f"(c[0]), "+f"(c[1]), "+f"(c[2]), "+f"(c[3])
        : "r"(a[0]), "r"(a[1]), "r"(a[2]), "r"(a[3]), "r"(b0), "r"(b1));
}

// rp-table GEMM chunk: rp[r][j] = q[r,:] . pt[j,:]
template<int NB0, int NBN>
__device__ __forceinline__ void rp_mma_chunk(const unsigned aq[8][4], const float* ptt,
                                             float* rp, int r0, int r1, int u, int g) {
    float c[NBN][4];
    #pragma unroll
    for (int n = 0; n < NBN; n++) { c[n][0]=0.f; c[n][1]=0.f; c[n][2]=0.f; c[n][3]=0.f; }
    #pragma unroll
    for (int s = 0; s < 8; s++) {
        #pragma unroll
        for (int n = 0; n < NBN; n++) {
            int jr = (NB0 + n) * 8 + g;
            unsigned b0 = __float_as_uint(ptt[(8*s + u)     * PT_STRIDE + jr]);
            unsigned b1 = __float_as_uint(ptt[(8*s + u + 4) * PT_STRIDE + jr]);
            mma_tf32(c[n], aq[s], b0, b1);
        }
    }
    #pragma unroll
    for (int n = 0; n < NBN; n++) {
        int col = (NB0 + n) * 8 + 2 * u;
        if (col <= 128)     { rp[r0*RP_STRIDE + col]     = c[n][0]; rp[r1*RP_STRIDE + col]     = c[n][2]; }
        if (col + 1 <= 128) { rp[r0*RP_STRIDE + col + 1] = c[n][1]; rp[r1*RP_STRIDE + col + 1] = c[n][3]; }
    }
}

__global__ void __launch_bounds__(NT, 3)
attn_tc_kernel(const float* __restrict__ q,
               const float* __restrict__ k,
               const float* __restrict__ v,
               const float* __restrict__ pt,
               float* __restrict__ out) {
    extern __shared__ float sm[];
    float* ks  = sm + KS_OFF;
    float* vs  = sm + VS_OFF;
    float* rp  = sm + RP_OFF;
    float* ptt = sm + PT_OFF;

    const int tid  = threadIdx.x;
    const int lane = tid & 31;
    const int w    = tid >> 5;       // warp 0..3
    const int u    = lane & 3;       // quad lane
    const int g    = lane >> 2;      // group 0..7
    const int qt   = blockIdx.x, b = blockIdx.y;
    const int qg0  = qt * TQ;
    const int r0   = 16 * w + g;     // tile-local rows owned by this thread
    const int r1   = r0 + 8;
    const int keysel = (g >> 1) + 4 * (g & 1);   // sigma(g): key permutation within 8-block

    // ---- phase 0: stage transposed tf32 pos_table (aliases ks/vs region) ----
    {
        const float4* ptg = (const float4*)pt;
        for (int i = tid; i < 129 * 16; i += NT) {
            int j = i >> 4, c0 = (i & 15) * 4;
            float4 p4 = ptg[i];
            ptt[(c0 + 0) * PT_STRIDE + j] = __uint_as_float(f2tf(p4.x));
            ptt[(c0 + 1) * PT_STRIDE + j] = __uint_as_float(f2tf(p4.y));
            ptt[(c0 + 2) * PT_STRIDE + j] = __uint_as_float(f2tf(p4.z));
            ptt[(c0 + 3) * PT_STRIDE + j] = __uint_as_float(f2tf(p4.w));
        }
        for (int i = tid; i < 64 * 7; i += NT)      // zero-pad j = 129..135
            ptt[(i / 7) * PT_STRIDE + 129 + (i % 7)] = 0.f;
    }

    // ---- Q fragments straight from gmem (one-time scattered loads) ----
    unsigned aq[8][4];
    {
        const float* q0 = q + (size_t)(b * SS + qg0 + r0) * DD;
        const float* q1 = q + (size_t)(b * SS + qg0 + r1) * DD;
        #pragma unroll
        for (int s = 0; s < 8; s++) {
            aq[s][0] = f2tf(q0[8*s + u]);
            aq[s][1] = f2tf(q1[8*s + u]);
            aq[s][2] = f2tf(q0[8*s + u + 4]);
            aq[s][3] = f2tf(q1[8*s + u + 4]);
        }
    }
    __syncthreads();

    // ---- phase 1: rp table via MMA ----
    rp_mma_chunk<0, 9>(aq, ptt, rp, r0, r1, u, g);
    rp_mma_chunk<9, 8>(aq, ptt, rp, r0, r1, u, g);
    __syncthreads();

    const float rpn0 = rp[r0 * RP_STRIDE + 0],   rpn1 = rp[r1 * RP_STRIDE + 0];
    const float rpp0 = rp[r0 * RP_STRIDE + 128], rpp1 = rp[r1 * RP_STRIDE + 128];

    float m0 = -1e30f, m1 = -1e30f, l0 = 0.f, l1 = 0.f;
    float co[8][4];
    #pragma unroll
    for (int j = 0; j < 8; j++) { co[j][0]=0.f; co[j][1]=0.f; co[j][2]=0.f; co[j][3]=0.f; }

    const unsigned* mrow0 = g_mbits + (size_t)(b * SS + qg0 + r0) * (SS / 32);
    const unsigned* mrow1 = g_mbits + (size_t)(b * SS + qg0 + r1) * (SS / 32);
    const float4* kg = (const float4*)(k + (size_t)b * SS * DD);
    const float4* vg = (const float4*)(v + (size_t)b * SS * DD);

    for (int kt = 0; kt < SS / TK; kt++) {
        const int kg0 = kt * TK;
        const int D   = kg0 - qg0;

        // ---- prefetch mask words early (latency overlapped with staging+MMA) ----
        const unsigned mw0a = mrow0[2*kt], mw0b = mrow0[2*kt + 1];
        const unsigned mw1a = mrow1[2*kt], mw1b = mrow1[2*kt + 1];

        __syncthreads();   // previous tile fully consumed

        // ---- stage K (stride 68) / V (stride 72), converted to tf32 bits ----
        for (int i = tid; i < TK * 16; i += NT) {
            int key = i >> 4, c0 = (i & 15) * 4;
            float4 kv = kg[kg0 * 16 + i];
            float4 vv = vg[kg0 * 16 + i];
            float* kd = ks + key * KS_STRIDE + c0;
            kd[0] = __uint_as_float(f2tf(kv.x)); kd[1] = __uint_as_float(f2tf(kv.y));
            kd[2] = __uint_as_float(f2tf(kv.z)); kd[3] = __uint_as_float(f2tf(kv.w));
            float* vd = vs + key * VS_STRIDE + c0;
            vd[0] = __uint_as_float(f2tf(vv.x)); vd[1] = __uint_as_float(f2tf(vv.y));
            vd[2] = __uint_as_float(f2tf(vv.z)); vd[3] = __uint_as_float(f2tf(vv.w));
        }
        __syncthreads();

        // ---- QK^T: c[j] covers keys {8j+u, 8j+u+4} x rows {r0, r1} (sigma layout) ----
        float c[8][4];
        #pragma unroll
        for (int j = 0; j < 8; j++) { c[j][0]=0.f; c[j][1]=0.f; c[j][2]=0.f; c[j][3]=0.f; }
        #pragma unroll
        for (int s = 0; s < 8; s++) {
            #pragma unroll
            for (int j = 0; j < 8; j++) {
                unsigned b0 = __float_as_uint(ks[(8*j + keysel) * KS_STRIDE + 8*s + u]);
                unsigned b1 = __float_as_uint(ks[(8*j + keysel) * KS_STRIDE + 8*s + u + 4]);
                mma_tf32(c[j], aq[s], b0, b1);
            }
        }

        // ---- epilogue: rel-pos + scale + mask ----
        const bool nearT = (D >= -64) && (D <= 64);
        #pragma unroll
        for (int j = 0; j < 8; j++) {
            const int col0 = 8*j + u, col1 = col0 + 4;
            float rv00, rv01, rv10, rv11;
            if (nearT) {
                int i00 = min(max(D + col0 - r0, -64), 64) + 64;
                int i01 = min(max(D + col1 - r0, -64), 64) + 64;
                int i10 = min(max(D + col0 - r1, -64), 64) + 64;
                int i11 = min(max(D + col1 - r1, -64), 64) + 64;
                rv00 = rp[r0 * RP_STRIDE + i00]; rv01 = rp[r0 * RP_STRIDE + i01];
                rv10 = rp[r1 * RP_STRIDE + i10]; rv11 = rp[r1 * RP_STRIDE + i11];
            } else if (D > 0) {
                rv00 = rpp0; rv01 = rpp0; rv10 = rpp1; rv11 = rpp1;
            } else {
                rv00 = rpn0; rv01 = rpn0; rv10 = rpn1; rv11 = rpn1;
            }
            float s00 = (c[j][0] + rv00) * 0.125f;
            float s01 = (c[j][1] + rv01) * 0.125f;
            float s10 = (c[j][2] + rv10) * 0.125f;
            float s11 = (c[j][3] + rv11) * 0.125f;
            const unsigned w0 = (j < 4) ? mw0a : mw0b;
            const unsigned w1 = (j < 4) ? mw1a : mw1b;
            if ((w0 >> (col0 & 31)) & 1) s00 = -3.0e38f;
            if ((w0 >> (col1 & 31)) & 1) s01 = -3.0e38f;
            if ((w1 >> (col0 & 31)) & 1) s10 = -3.0e38f;
            if ((w1 >> (col1 & 31)) & 1) s11 = -3.0e38f;
            c[j][0] = s00; c[j][1] = s01; c[j][2] = s10; c[j][3] = s11;
        }

        // ---- online softmax (row reductions stay inside the quad) ----
        float t0 = -3.0e38f, t1 = -3.0e38f;
        #pragma unroll
        for (int j = 0; j < 8; j++) {
            t0 = fmaxf(t0, fmaxf(c[j][0], c[j][1]));
            t1 = fmaxf(t1, fmaxf(c[j][2], c[j][3]));
        }
        t0 = fmaxf(t0, __shfl_xor_sync(0xffffffffu, t0, 1));
        t0 = fmaxf(t0, __shfl_xor_sync(0xffffffffu, t0, 2));
        t1 = fmaxf(t1, __shfl_xor_sync(0xffffffffu, t1, 1));
        t1 = fmaxf(t1, __shfl_xor_sync(0xffffffffu, t1, 2));

        const float mn0 = fmaxf(m0, t0), mn1 = fmaxf(m1, t1);
        const float al0 = __expf(m0 - mn0), al1 = __expf(m1 - mn1);
        float ps0 = 0.f, ps1 = 0.f;
        #pragma unroll
        for (int j = 0; j < 8; j++) {
            float p00 = __expf(c[j][0] - mn0);
            float p01 = __expf(c[j][1] - mn0);
            float p10 = __expf(c[j][2] - mn1);
            float p11 = __expf(c[j][3] - mn1);
            ps0 += p00 + p01; ps1 += p10 + p11;
            c[j][0] = p00; c[j][1] = p01; c[j][2] = p10; c[j][3] = p11;
        }
        ps0 += __shfl_xor_sync(0xffffffffu, ps0, 1);
        ps0 += __shfl_xor_sync(0xffffffffu, ps0, 2);
        ps1 += __shfl_xor_sync(0xffffffffu, ps1, 1);
        ps1 += __shfl_xor_sync(0xffffffffu, ps1, 2);
        l0 = l0 * al0 + ps0; m0 = mn0;
        l1 = l1 * al1 + ps1; m1 = mn1;
        #pragma unroll
        for (int j = 0; j < 8; j++) {
            co[j][0] *= al0; co[j][1] *= al0;
            co[j][2] *= al1; co[j][3] *= al1;
        }

        // ---- PV: A frags = pure register renaming of P (sigma layout) ----
        #pragma unroll
        for (int s = 0; s < 8; s++) {
            unsigned a[4] = { f2tf(c[s][0]), f2tf(c[s][2]), f2tf(c[s][1]), f2tf(c[s][3]) };
            #pragma unroll
            for (int j = 0; j < 8; j++) {
                unsigned b0 = __float_as_uint(vs[(8*s + u)     * VS_STRIDE + 8*j + g]);
                unsigned b1 = __float_as_uint(vs[(8*s + u + 4) * VS_STRIDE + 8*j + g]);
                mma_tf32(co[j], a, b0, b1);
            }
        }
    }

    // ---- finalize ----
    const float il0 = 1.0f / l0, il1 = 1.0f / l1;
    float* o0 = out + (size_t)(b * SS + qg0 + r0) * DD;
    float* o1 = out + (size_t)(b * SS + qg0 + r1) * DD;
    #pragma unroll
    for (int j = 0; j < 8; j++) {
        int col = 8*j + 2*u;
        float2 v0; v0.x = co[j][0] * il0; v0.y = co[j][1] * il0;
        float2 v1; v1.x = co[j][2] * il1; v1.y = co[j][3] * il1;
        *(float2*)(o0 + col) = v0;
        *(float2*)(o1 + col) = v1;
    }
}

extern "C" void kernel_launch(void* const* d_in, const int* in_sizes, int n_in,
                              void* d_out, int out_size) {
    const float* q    = (const float*)d_in[0];
    const float* k    = (const float*)d_in[1];
    const float* v    = (const float*)d_in[2];
    const int*   mask = (const int*)d_in[3];
    const float* pt   = (const float*)d_in[4];
    float*       out  = (float*)d_out;

    // 1M mask words, 1 word per thread
    pack_mask_kernel<<<(BB * SS * SS / 32) / 256, 256>>>(mask);

    size_t smem = SMEM_FLOATS * sizeof(float);
    cudaFuncSetAttribute(attn_tc_kernel,
                         cudaFuncAttributeMaxDynamicSharedMemorySize, (int)smem);
    dim3 grid(SS / TQ, BB);
    attn_tc_kernel<<<grid, NT, smem>>>(q, k, v, pt, out);
}

// round 6
// speedup vs baseline: 5.6496x; 1.0778x over previous
#include <cuda_runtime.h>
#include <cstdint>

#define BB 32
#define SS 1024
#define DD 64
#define TQ 64
#define TK 64
#define NT 128

#define KS_STRIDE 68
#define VS_STRIDE 72
#define RP_STRIDE 129
#define PT_STRIDE 136

// smem float offsets
#define KS_OFF  0                            // K tf32, 64 x 68
#define VS0_OFF (KS_OFF + 64*KS_STRIDE)      // 4352  V raw fp32 buf0, 64 x 72
#define VS1_OFF (VS0_OFF + 64*VS_STRIDE)     // 8960  V raw fp32 buf1
#define RP_OFF  (VS1_OFF + 64*VS_STRIDE)     // 13568
#define SMEM_FLOATS (RP_OFF + 64*RP_STRIDE)  // 21824 floats = 87296 B -> 2 CTAs/SM
#define PT_OFF KS_OFF                        // ptt aliases K+V0+V1 region (8704 <= 13568)

__device__ unsigned g_mbits[(size_t)BB * SS * SS / 32];   // 4 MB packed mask bits

// ---- mask bit-pack v2: coalesced int4 loads + nibble shuffle-OR ----
__global__ void pack_mask_kernel(const int* __restrict__ mask) {
    size_t i4 = (size_t)blockIdx.x * blockDim.x + threadIdx.x;   // int4 index
    int4 v = ((const int4*)mask)[i4];
    unsigned nib = (v.x != 0 ? 1u : 0u) | (v.y != 0 ? 2u : 0u)
                 | (v.z != 0 ? 4u : 0u) | (v.w != 0 ? 8u : 0u);
    unsigned word = nib << ((threadIdx.x & 7) * 4);
    word |= __shfl_xor_sync(0xffffffffu, word, 1);
    word |= __shfl_xor_sync(0xffffffffu, word, 2);
    word |= __shfl_xor_sync(0xffffffffu, word, 4);
    if ((threadIdx.x & 7) == 0) g_mbits[i4 >> 3] = word;
}

__device__ __forceinline__ unsigned f2tf(float f) {
    unsigned u; asm("cvt.rna.tf32.f32 %0, %1;" : "=r"(u) : "f"(f)); return u;
}
__device__ __forceinline__ void mma_tf32(float c[4], const unsigned a[4],
                                         unsigned b0, unsigned b1) {
    asm volatile(
        "mma.sync.aligned.m16n8k8.row.col.f32.tf32.tf32.f32 "
        "{%0,%1,%2,%3}, {%4,%5,%6,%7}, {%8,%9}, {%0,%1,%2,%3};"
        : "+f"(c[0]), "+f"(c[1]), "+f"(c[2]), "+f"(c[3])
        : "r"(a[0]), "r"(a[1]), "r"(a[2]), "r"(a[3]), "r"(b0), "r"(b1));
}
__device__ __forceinline__ void cpa16(unsigned s, const void* g) {
    asm volatile("cp.async.cg.shared.global [%0], [%1], 16;" :: "r"(s), "l"(g));
}
#define CP_COMMIT() asm volatile("cp.async.commit_group;")
#define CP_WAIT(n)  asm volatile("cp.async.wait_group %0;" :: "n"(n))

// rp-table GEMM chunk: rp[r][j] = q[r,:] . pt[j,:]
template<int NB0, int NBN>
__device__ __forceinline__ void rp_mma_chunk(const unsigned aq[8][4], const float* ptt,
                                             float* rp, int r0, int r1, int u, int g) {
    float c[NBN][4];
    #pragma unroll
    for (int n = 0; n < NBN; n++) { c[n][0]=0.f; c[n][1]=0.f; c[n][2]=0.f; c[n][3]=0.f; }
    #pragma unroll
    for (int s = 0; s < 8; s++) {
        #pragma unroll
        for (int n = 0; n < NBN; n++) {
            int jr = (NB0 + n) * 8 + g;
            unsigned b0 = __float_as_uint(ptt[(8*s + u)     * PT_STRIDE + jr]);
            unsigned b1 = __float_as_uint(ptt[(8*s + u + 4) * PT_STRIDE + jr]);
            mma_tf32(c[n], aq[s], b0, b1);
        }
    }
    #pragma unroll
    for (int n = 0; n < NBN; n++) {
        int col = (NB0 + n) * 8 + 2 * u;
        if (col <= 128)     { rp[r0*RP_STRIDE + col]     = c[n][0]; rp[r1*RP_STRIDE + col]     = c[n][2]; }
        if (col + 1 <= 128) { rp[r0*RP_STRIDE + col + 1] = c[n][1]; rp[r1*RP_STRIDE + col + 1] = c[n][3]; }
    }
}

__global__ void __launch_bounds__(NT, 2)
attn_tc_kernel(const float* __restrict__ q,
               const float* __restrict__ k,
               const float* __restrict__ v,
               const float* __restrict__ pt,
               float* __restrict__ out) {
    extern __shared__ float sm[];
    float* ks  = sm + KS_OFF;
    float* rp  = sm + RP_OFF;
    float* ptt = sm + PT_OFF;

    const int tid  = threadIdx.x;
    const int lane = tid & 31;
    const int w    = tid >> 5;
    const int u    = lane & 3;
    const int g    = lane >> 2;
    const int qt   = blockIdx.x, b = blockIdx.y;
    const int qg0  = qt * TQ;
    const int r0   = 16 * w + g;
    const int r1   = r0 + 8;
    const int keysel = (g >> 1) + 4 * (g & 1);   // sigma(g)

    const float4* kg = (const float4*)(k + (size_t)b * SS * DD);
    const float4* vg = (const float4*)(v + (size_t)b * SS * DD);

    // ---- phase 0: stage transposed tf32 pos_table (aliases K/V region) ----
    {
        const float4* ptg = (const float4*)pt;
        for (int i = tid; i < 129 * 16; i += NT) {
            int j = i >> 4, c0 = (i & 15) * 4;
            float4 p4 = ptg[i];
            ptt[(c0 + 0) * PT_STRIDE + j] = __uint_as_float(f2tf(p4.x));
            ptt[(c0 + 1) * PT_STRIDE + j] = __uint_as_float(f2tf(p4.y));
            ptt[(c0 + 2) * PT_STRIDE + j] = __uint_as_float(f2tf(p4.z));
            ptt[(c0 + 3) * PT_STRIDE + j] = __uint_as_float(f2tf(p4.w));
        }
        for (int i = tid; i < 64 * 7; i += NT)
            ptt[(i / 7) * PT_STRIDE + 129 + (i % 7)] = 0.f;
    }

    // ---- Q fragments straight from gmem ----
    unsigned aq[8][4];
    {
        const float* q0 = q + (size_t)(b * SS + qg0 + r0) * DD;
        const float* q1 = q + (size_t)(b * SS + qg0 + r1) * DD;
        #pragma unroll
        for (int s = 0; s < 8; s++) {
            aq[s][0] = f2tf(q0[8*s + u]);
            aq[s][1] = f2tf(q1[8*s + u]);
            aq[s][2] = f2tf(q0[8*s + u + 4]);
            aq[s][3] = f2tf(q1[8*s + u + 4]);
        }
    }
    __syncthreads();

    // ---- phase 1: rp table via MMA ----
    rp_mma_chunk<0, 9>(aq, ptt, rp, r0, r1, u, g);
    rp_mma_chunk<9, 8>(aq, ptt, rp, r0, r1, u, g);
    __syncthreads();

    const float rpn0 = rp[r0 * RP_STRIDE + 0],   rpn1 = rp[r1 * RP_STRIDE + 0];
    const float rpp0 = rp[r0 * RP_STRIDE + 128], rpp1 = rp[r1 * RP_STRIDE + 128];

    // ---- prologue staging: cp.async V0 (raw), direct K0 (cvt+STS) ----
    {
        #pragma unroll
        for (int l = 0; l < 8; l++) {
            int i = tid + l * NT, row = i >> 4, c4 = i & 15;
            unsigned dst = (unsigned)__cvta_generic_to_shared(sm + VS0_OFF + row * VS_STRIDE + c4 * 4);
            cpa16(dst, vg + i);
        }
        CP_COMMIT();
        #pragma unroll
        for (int l = 0; l < 8; l++) {
            int i = tid + l * NT, row = i >> 4, c4 = i & 15;
            float4 kv = kg[i];
            float* kd = ks + row * KS_STRIDE + c4 * 4;
            kd[0] = __uint_as_float(f2tf(kv.x)); kd[1] = __uint_as_float(f2tf(kv.y));
            kd[2] = __uint_as_float(f2tf(kv.z)); kd[3] = __uint_as_float(f2tf(kv.w));
        }
        CP_WAIT(0);
    }
    __syncthreads();

    float m0 = -1e30f, m1 = -1e30f, l0 = 0.f, l1 = 0.f;
    float co[8][4];
    #pragma unroll
    for (int j = 0; j < 8; j++) { co[j][0]=0.f; co[j][1]=0.f; co[j][2]=0.f; co[j][3]=0.f; }

    const unsigned* mrow0 = g_mbits + (size_t)(b * SS + qg0 + r0) * (SS / 32);
    const unsigned* mrow1 = g_mbits + (size_t)(b * SS + qg0 + r1) * (SS / 32);

    float4 pk[8];

    for (int kt = 0; kt < SS / TK; kt++) {
        const int kg0 = kt * TK;
        const int D   = kg0 - qg0;
        const float* vcur = sm + ((kt & 1) ? VS1_OFF : VS0_OFF);

        // ---- prefetch mask words (latency overlapped) ----
        const unsigned mw0a = mrow0[2*kt], mw0b = mrow0[2*kt + 1];
        const unsigned mw1a = mrow1[2*kt], mw1b = mrow1[2*kt + 1];

        // ---- issue next tile: V via cp.async, K into registers ----
        if (kt < 15) {
            float* vnext = sm + (((kt + 1) & 1) ? VS1_OFF : VS0_OFF);
            #pragma unroll
            for (int l = 0; l < 8; l++) {
                int i = tid + l * NT, row = i >> 4, c4 = i & 15;
                unsigned dst = (unsigned)__cvta_generic_to_shared(vnext + row * VS_STRIDE + c4 * 4);
                cpa16(dst, vg + (kg0 + TK) * 16 + i);
            }
            #pragma unroll
            for (int l = 0; l < 8; l++)
                pk[l] = kg[(kg0 + TK) * 16 + tid + l * NT];
        }
        CP_COMMIT();

        // ---- QK^T from staged K ----
        float c[8][4];
        #pragma unroll
        for (int j = 0; j < 8; j++) { c[j][0]=0.f; c[j][1]=0.f; c[j][2]=0.f; c[j][3]=0.f; }
        #pragma unroll
        for (int s = 0; s < 8; s++) {
            #pragma unroll
            for (int j = 0; j < 8; j++) {
                unsigned b0 = __float_as_uint(ks[(8*j + keysel) * KS_STRIDE + 8*s + u]);
                unsigned b1 = __float_as_uint(ks[(8*j + keysel) * KS_STRIDE + 8*s + u + 4]);
                mma_tf32(c[j], aq[s], b0, b1);
            }
        }

        // ---- epilogue: rel-pos + scale + mask ----
        const bool nearT = (D >= -64) && (D <= 64);
        #pragma unroll
        for (int j = 0; j < 8; j++) {
            const int col0 = 8*j + u, col1 = col0 + 4;
            float rv00, rv01, rv10, rv11;
            if (nearT) {
                int i00 = min(max(D + col0 - r0, -64), 64) + 64;
                int i01 = min(max(D + col1 - r0, -64), 64) + 64;
                int i10 = min(max(D + col0 - r1, -64), 64) + 64;
                int i11 = min(max(D + col1 - r1, -64), 64) + 64;
                rv00 = rp[r0 * RP_STRIDE + i00]; rv01 = rp[r0 * RP_STRIDE + i01];
                rv10 = rp[r1 * RP_STRIDE + i10]; rv11 = rp[r1 * RP_STRIDE + i11];
            } else if (D > 0) {
                rv00 = rpp0; rv01 = rpp0; rv10 = rpp1; rv11 = rpp1;
            } else {
                rv00 = rpn0; rv01 = rpn0; rv10 = rpn1; rv11 = rpn1;
            }
            float s00 = (c[j][0] + rv00) * 0.125f;
            float s01 = (c[j][1] + rv01) * 0.125f;
            float s10 = (c[j][2] + rv10) * 0.125f;
            float s11 = (c[j][3] + rv11) * 0.125f;
            const unsigned w0 = (j < 4) ? mw0a : mw0b;
            const unsigned w1 = (j < 4) ? mw1a : mw1b;
            if ((w0 >> (col0 & 31)) & 1) s00 = -3.0e38f;
            if ((w0 >> (col1 & 31)) & 1) s01 = -3.0e38f;
            if ((w1 >> (col0 & 31)) & 1) s10 = -3.0e38f;
            if ((w1 >> (col1 & 31)) & 1) s11 = -3.0e38f;
            c[j][0] = s00; c[j][1] = s01; c[j][2] = s10; c[j][3] = s11;
        }

        // ---- online softmax ----
        float t0 = -3.0e38f, t1 = -3.0e38f;
        #pragma unroll
        for (int j = 0; j < 8; j++) {
            t0 = fmaxf(t0, fmaxf(c[j][0], c[j][1]));
            t1 = fmaxf(t1, fmaxf(c[j][2], c[j][3]));
        }
        t0 = fmaxf(t0, __shfl_xor_sync(0xffffffffu, t0, 1));
        t0 = fmaxf(t0, __shfl_xor_sync(0xffffffffu, t0, 2));
        t1 = fmaxf(t1, __shfl_xor_sync(0xffffffffu, t1, 1));
        t1 = fmaxf(t1, __shfl_xor_sync(0xffffffffu, t1, 2));

        const float mn0 = fmaxf(m0, t0), mn1 = fmaxf(m1, t1);
        const float al0 = __expf(m0 - mn0), al1 = __expf(m1 - mn1);
        float ps0 = 0.f, ps1 = 0.f;
        #pragma unroll
        for (int j = 0; j < 8; j++) {
            float p00 = __expf(c[j][0] - mn0);
            float p01 = __expf(c[j][1] - mn0);
            float p10 = __expf(c[j][2] - mn1);
            float p11 = __expf(c[j][3] - mn1);
            ps0 += p00 + p01; ps1 += p10 + p11;
            c[j][0] = p00; c[j][1] = p01; c[j][2] = p10; c[j][3] = p11;
        }
        ps0 += __shfl_xor_sync(0xffffffffu, ps0, 1);
        ps0 += __shfl_xor_sync(0xffffffffu, ps0, 2);
        ps1 += __shfl_xor_sync(0xffffffffu, ps1, 1);
        ps1 += __shfl_xor_sync(0xffffffffu, ps1, 2);
        l0 = l0 * al0 + ps0; m0 = mn0;
        l1 = l1 * al1 + ps1; m1 = mn1;
        #pragma unroll
        for (int j = 0; j < 8; j++) {
            co[j][0] *= al0; co[j][1] *= al0;
            co[j][2] *= al1; co[j][3] *= al1;
        }

        // ---- V[kt] landed; make visible; stage K[kt+1] from prefetch regs ----
        CP_WAIT(1);
        __syncthreads();
        if (kt < 15) {
            #pragma unroll
            for (int l = 0; l < 8; l++) {
                int i = tid + l * NT, row = i >> 4, c4 = i & 15;
                float* kd = ks + row * KS_STRIDE + c4 * 4;
                kd[0] = __uint_as_float(f2tf(pk[l].x)); kd[1] = __uint_as_float(f2tf(pk[l].y));
                kd[2] = __uint_as_float(f2tf(pk[l].z)); kd[3] = __uint_as_float(f2tf(pk[l].w));
            }
        }

        // ---- PV: A frags renamed from P; V converted at fragment load ----
        #pragma unroll
        for (int s = 0; s < 8; s++) {
            unsigned a[4] = { f2tf(c[s][0]), f2tf(c[s][2]), f2tf(c[s][1]), f2tf(c[s][3]) };
            #pragma unroll
            for (int j = 0; j < 8; j++) {
                unsigned b0 = f2tf(vcur[(8*s + u)     * VS_STRIDE + 8*j + g]);
                unsigned b1 = f2tf(vcur[(8*s + u + 4) * VS_STRIDE + 8*j + g]);
                mma_tf32(co[j], a, b0, b1);
            }
        }
        __syncthreads();   // K STS visible before next QK; V buffer free for reuse
    }

    // ---- finalize ----
    const float il0 = 1.0f / l0, il1 = 1.0f / l1;
    float* o0 = out + (size_t)(b * SS + qg0 + r0) * DD;
    float* o1 = out + (size_t)(b * SS + qg0 + r1) * DD;
    #pragma unroll
    for (int j = 0; j < 8; j++) {
        int col = 8*j + 2*u;
        float2 v0; v0.x = co[j][0] * il0; v0.y = co[j][1] * il0;
        float2 v1; v1.x = co[j][2] * il1; v1.y = co[j][3] * il1;
        *(float2*)(o0 + col) = v0;
        *(float2*)(o1 + col) = v1;
    }
}

extern "C" void kernel_launch(void* const* d_in, const int* in_sizes, int n_in,
                              void* d_out, int out_size) {
    const float* q    = (const float*)d_in[0];
    const float* k    = (const float*)d_in[1];
    const float* v    = (const float*)d_in[2];
    const int*   mask = (const int*)d_in[3];
    const float* pt   = (const float*)d_in[4];
    float*       out  = (float*)d_out;

    // 8M int4 chunks, 1 per thread
    pack_mask_kernel<<<(BB * SS * SS / 4) / 256, 256>>>(mask);

    size_t smem = SMEM_FLOATS * sizeof(float);
    cudaFuncSetAttribute(attn_tc_kernel,
                         cudaFuncAttributeMaxDynamicSharedMemorySize, (int)smem);
    dim3 grid(SS / TQ, BB);
    attn_tc_kernel<<<grid, NT, smem>>>(q, k, v, pt, out);
}